// round 4
// baseline (speedup 1.0000x reference)
#include <cuda_runtime.h>
#include <cuda_fp16.h>
#include <cstdint>
#include <cstddef>

// ---------------- problem constants ----------------
#define TOK 16384
#define HD  2048
#define ID  4096
#define NG  4

// ---------------- device scratch ----------------
__device__ __half g_bufA[(size_t)TOK * ID];
__device__ __half g_bufB[(size_t)TOK * ID];
__device__ __half g_w1h [(size_t)ID * HD];
__device__ __half g_w2h [(size_t)HD * ID];
__device__ __half g_l0g1[(size_t)NG * ID * HD];
__device__ __half g_l0g2[(size_t)NG * HD * ID];
__device__ __half g_l1g1[(size_t)NG * ID * HD];
__device__ __half g_l1g2[(size_t)NG * HD * ID];

// ---------------- fp32 -> fp16 conversion ----------------
__global__ void f2h_kernel(const float4* __restrict__ src, __half2* __restrict__ dst, size_t n4) {
    size_t i = (size_t)blockIdx.x * blockDim.x + threadIdx.x;
    if (i < n4) {
        float4 v = src[i];
        dst[2 * i]     = __floats2half2_rn(v.x, v.y);
        dst[2 * i + 1] = __floats2half2_rn(v.z, v.w);
    }
}

// ---------------- tile config ----------------
constexpr int BM = 128, BN = 256, BK = 64;
constexpr int STAGES = 3;
// rows are 64 halfs = 128 bytes; XOR swizzle, no padding
constexpr int ASTG = BM * 128;              // 16384 B
constexpr int BSTG = BN * 128;              // 32768 B
constexpr int STG  = ASTG + BSTG;           // 49152 B per stage
constexpr int SMEM_BYTES = STAGES * STG;    // 147456 B

// ---------------- helpers ----------------
__device__ __forceinline__ uint32_t h2u(__half2 h) {
    union { __half2 h; uint32_t u; } c; c.h = h; return c.u;
}
__device__ __forceinline__ uint32_t smem_u32(const void* p) {
    return (uint32_t)__cvta_generic_to_shared(p);
}
__device__ __forceinline__ uint32_t swz(uint32_t off) {   // SW128-style XOR swizzle
    return off ^ ((off >> 3) & 0x70);
}
__device__ __forceinline__ void cp16(uint32_t dst, const void* src) {
    asm volatile("cp.async.cg.shared.global [%0], [%1], 16;\n" :: "r"(dst), "l"(src));
}
__device__ __forceinline__ void cp_commit() { asm volatile("cp.async.commit_group;\n"); }
template <int N>
__device__ __forceinline__ void cp_wait() { asm volatile("cp.async.wait_group %0;\n" :: "n"(N)); }

__device__ __forceinline__ void ldsm_x4(uint32_t* r, uint32_t addr) {
    asm volatile("ldmatrix.sync.aligned.m8n8.x4.shared.b16 {%0,%1,%2,%3}, [%4];\n"
                 : "=r"(r[0]), "=r"(r[1]), "=r"(r[2]), "=r"(r[3]) : "r"(addr));
}
__device__ __forceinline__ void mma16816(float* c, const uint32_t* a, const uint32_t* b) {
    asm volatile("mma.sync.aligned.m16n8k16.row.col.f32.f16.f16.f32 "
                 "{%0,%1,%2,%3}, {%4,%5,%6,%7}, {%8,%9}, {%0,%1,%2,%3};\n"
                 : "+f"(c[0]), "+f"(c[1]), "+f"(c[2]), "+f"(c[3])
                 : "r"(a[0]), "r"(a[1]), "r"(a[2]), "r"(a[3]), "r"(b[0]), "r"(b[1]));
}

// ---------------- fp16 GEMM:  C[M,N] = A[M,K] * W[N,K]^T + bias ----------------
// grid = (N/BN, M/BM). Grouped along M: group = bm / mRowsPerGroup.
template <typename OutT>
__global__ __launch_bounds__(256, 1)
void gemm_kernel(const __half* __restrict__ A, const __half* __restrict__ W,
                 const float* __restrict__ bias, OutT* __restrict__ C,
                 int N, int K, int mRowsPerGroup) {
    extern __shared__ char smem_raw[];
    const uint32_t sbase = smem_u32(smem_raw);

    const int tid  = threadIdx.x;
    const int lane = tid & 31;
    const int warp = tid >> 5;
    const int wm   = warp & 1;    // 2 x 64 rows
    const int wn   = warp >> 1;   // 4 x 64 cols
    const int bm   = blockIdx.y * BM;
    const int bn   = blockIdx.x * BN;
    const int group = bm / mRowsPerGroup;

    const __half* gA = A + (size_t)bm * K;
    const __half* gW = W + (size_t)group * N * K + (size_t)bn * K;
    const float*  gBias = bias + (size_t)group * N + bn;
    const int kTiles = K / BK;

    float acc[4][8][4];
#pragma unroll
    for (int a = 0; a < 4; a++)
#pragma unroll
        for (int b = 0; b < 8; b++)
#pragma unroll
            for (int c = 0; c < 4; c++) acc[a][b][c] = 0.f;

    auto load_stage = [&](int s, int kt) {
        const uint32_t dA = sbase + s * STG;
        const uint32_t dB = dA + ASTG;
        const __half* srcA = gA + kt * BK;
        const __half* srcB = gW + kt * BK;
#pragma unroll
        for (int i = 0; i < 4; i++) {       // A: 1024 chunks of 16B
            int q = tid + i * 256;
            int r = q >> 3, c = q & 7;
            cp16(dA + swz((uint32_t)(r * 128 + c * 16)), srcA + (size_t)r * K + c * 8);
        }
#pragma unroll
        for (int i = 0; i < 8; i++) {       // B: 2048 chunks of 16B
            int q = tid + i * 256;
            int r = q >> 3, c = q & 7;
            cp16(dB + swz((uint32_t)(r * 128 + c * 16)), srcB + (size_t)r * K + c * 8);
        }
    };

    // prologue: 2 stages in flight
    load_stage(0, 0); cp_commit();
    if (kTiles > 1) load_stage(1, 1);
    cp_commit();

    for (int kt = 0; kt < kTiles; ++kt) {
        cp_wait<1>();          // stage kt resident
        __syncthreads();       // all warps done with stage (kt-1) -> safe to overwrite (kt+2)%3

        // issue next-stage loads BEFORE compute so they overlap the MMAs
        const int nk = kt + 2;
        if (nk < kTiles) load_stage(nk % STAGES, nk);
        cp_commit();

        const uint32_t cA = sbase + (kt % STAGES) * STG;
        const uint32_t cB = cA + ASTG;

#pragma unroll
        for (int ks = 0; ks < BK / 16; ++ks) {
            uint32_t aF[4][4], bF[8][2];
#pragma unroll
            for (int mi = 0; mi < 4; ++mi) {
                int r = wm * 64 + mi * 16 + (lane & 15);
                int c = ks * 16 + (lane >> 4) * 8;
                ldsm_x4(aF[mi], cA + swz((uint32_t)(r * 128 + c * 2)));
            }
#pragma unroll
            for (int nj = 0; nj < 4; ++nj) {   // each ldsm.x4 covers 16 n-cols
                int r = wn * 64 + nj * 16 + ((lane >> 4) & 1) * 8 + (lane & 7);
                int c = ks * 16 + ((lane >> 3) & 1) * 8;
                uint32_t t[4];
                ldsm_x4(t, cB + swz((uint32_t)(r * 128 + c * 2)));
                bF[2 * nj][0] = t[0]; bF[2 * nj][1] = t[1];
                bF[2 * nj + 1][0] = t[2]; bF[2 * nj + 1][1] = t[3];
            }
#pragma unroll
            for (int mi = 0; mi < 4; ++mi)
#pragma unroll
                for (int ni = 0; ni < 8; ++ni)
                    mma16816(acc[mi][ni], aF[mi], bF[ni]);
        }
    }

    // ---------------- epilogue: bias add + store ----------------
#pragma unroll
    for (int mi = 0; mi < 4; ++mi) {
#pragma unroll
        for (int ni = 0; ni < 8; ++ni) {
            int r0 = bm + wm * 64 + mi * 16 + (lane >> 2);
            int cb = wn * 64 + ni * 8 + (lane & 3) * 2;
            int c0 = bn + cb;
            float bv0 = gBias[cb], bv1 = gBias[cb + 1];
            float v0 = acc[mi][ni][0] + bv0;
            float v1 = acc[mi][ni][1] + bv1;
            float v2 = acc[mi][ni][2] + bv0;
            float v3 = acc[mi][ni][3] + bv1;
            if constexpr (sizeof(OutT) == 2) {
                *(__half2*)((__half*)C + (size_t)r0 * N + c0) =
                    __floats2half2_rn(v0, v1);
                *(__half2*)((__half*)C + (size_t)(r0 + 8) * N + c0) =
                    __floats2half2_rn(v2, v3);
            } else {
                *(float2*)((float*)C + (size_t)r0 * N + c0)       = make_float2(v0, v1);
                *(float2*)((float*)C + (size_t)(r0 + 8) * N + c0) = make_float2(v2, v3);
            }
        }
    }
}

// ---------------- host launcher ----------------
static inline void* sym_addr(const void* symbol) {
    void* p = nullptr;
    cudaGetSymbolAddress(&p, symbol);
    return p;
}

extern "C" void kernel_launch(void* const* d_in, const int* in_sizes, int n_in,
                              void* d_out, int out_size) {
    const float* x    = (const float*)d_in[0];
    const float* w1   = (const float*)d_in[1];
    const float* b1   = (const float*)d_in[2];
    const float* w2   = (const float*)d_in[3];
    const float* b2   = (const float*)d_in[4];
    const float* g1w0 = (const float*)d_in[5];
    const float* g1b0 = (const float*)d_in[6];
    const float* g2w0 = (const float*)d_in[7];
    const float* g2b0 = (const float*)d_in[8];
    const float* g1w1 = (const float*)d_in[9];
    const float* g1b1 = (const float*)d_in[10];
    const float* g2w1 = (const float*)d_in[11];
    const float* g2b1 = (const float*)d_in[12];

    __half* bufA = (__half*)sym_addr(g_bufA);
    __half* bufB = (__half*)sym_addr(g_bufB);
    __half* w1h  = (__half*)sym_addr(g_w1h);
    __half* w2h  = (__half*)sym_addr(g_w2h);
    __half* l0g1 = (__half*)sym_addr(g_l0g1);
    __half* l0g2 = (__half*)sym_addr(g_l0g2);
    __half* l1g1 = (__half*)sym_addr(g_l1g1);
    __half* l1g2 = (__half*)sym_addr(g_l1g2);

    cudaFuncSetAttribute(gemm_kernel<__half>, cudaFuncAttributeMaxDynamicSharedMemorySize, SMEM_BYTES);
    cudaFuncSetAttribute(gemm_kernel<float>,  cudaFuncAttributeMaxDynamicSharedMemorySize, SMEM_BYTES);

    auto conv = [&](const float* s, __half* d, size_t n) {
        size_t n4 = n / 4;
        unsigned blocks = (unsigned)((n4 + 255) / 256);
        f2h_kernel<<<blocks, 256>>>((const float4*)s, (__half2*)d, n4);
    };

    conv(x,    bufA, (size_t)TOK * HD);
    conv(w1,   w1h,  (size_t)ID * HD);
    conv(w2,   w2h,  (size_t)HD * ID);
    conv(g1w0, l0g1, (size_t)NG * ID * HD);
    conv(g2w0, l0g2, (size_t)NG * HD * ID);
    conv(g1w1, l1g1, (size_t)NG * ID * HD);
    conv(g2w1, l1g2, (size_t)NG * HD * ID);

    dim3 blk(256);
    // stage 1: dense w1  [16384,2048] x [4096,2048]^T -> [16384,4096]
    gemm_kernel<__half><<<dim3(ID / BN, TOK / BM), blk, SMEM_BYTES>>>(bufA, w1h, b1, bufB, ID, HD, TOK);
    // stage 2: dense w2 -> [16384,2048]
    gemm_kernel<__half><<<dim3(HD / BN, TOK / BM), blk, SMEM_BYTES>>>(bufB, w2h, b2, bufA, HD, ID, TOK);
    // layer 0 grouped
    gemm_kernel<__half><<<dim3(ID / BN, TOK / BM), blk, SMEM_BYTES>>>(bufA, l0g1, g1b0, bufB, ID, HD, TOK / NG);
    gemm_kernel<__half><<<dim3(HD / BN, TOK / BM), blk, SMEM_BYTES>>>(bufB, l0g2, g2b0, bufA, HD, ID, TOK / NG);
    // layer 1 grouped
    gemm_kernel<__half><<<dim3(ID / BN, TOK / BM), blk, SMEM_BYTES>>>(bufA, l1g1, g1b1, bufB, ID, HD, TOK / NG);
    // final: fp32 straight to d_out
    gemm_kernel<float><<<dim3(HD / BN, TOK / BM), blk, SMEM_BYTES>>>(bufB, l1g2, g2b1, (float*)d_out, HD, ID, TOK / NG);
}

// round 5
// speedup vs baseline: 1.0894x; 1.0894x over previous
#include <cuda_runtime.h>
#include <cuda_fp16.h>
#include <cstdint>
#include <cstddef>

// ---------------- problem constants ----------------
#define TOK 16384
#define HD  2048
#define ID  4096
#define NG  4

// ---------------- device scratch ----------------
__device__ __half g_bufA[(size_t)TOK * ID];
__device__ __half g_bufB[(size_t)TOK * ID];
__device__ __half g_w1h [(size_t)ID * HD];
__device__ __half g_w2h [(size_t)HD * ID];
__device__ __half g_l0g1[(size_t)NG * ID * HD];
__device__ __half g_l0g2[(size_t)NG * HD * ID];
__device__ __half g_l1g1[(size_t)NG * ID * HD];
__device__ __half g_l1g2[(size_t)NG * HD * ID];

// ---------------- fp32 -> fp16 conversion ----------------
__global__ void f2h_kernel(const float4* __restrict__ src, __half2* __restrict__ dst, size_t n4) {
    size_t i = (size_t)blockIdx.x * blockDim.x + threadIdx.x;
    if (i < n4) {
        float4 v = src[i];
        dst[2 * i]     = __floats2half2_rn(v.x, v.y);
        dst[2 * i + 1] = __floats2half2_rn(v.z, v.w);
    }
}

// ---------------- tile config ----------------
constexpr int BM = 128, BN = 128, BK = 64;
constexpr int STAGES = 3;
// rows: 64 halfs = 128B, XOR swizzle (no padding)
constexpr int ASTG = BM * 128;              // 16384 B
constexpr int BSTG = BN * 128;              // 16384 B
constexpr int STG  = ASTG + BSTG;           // 32768 B per stage
constexpr int SMEM_BYTES = STAGES * STG;    // 98304 B -> 2 CTAs / SM

// ---------------- helpers ----------------
__device__ __forceinline__ uint32_t smem_u32(const void* p) {
    return (uint32_t)__cvta_generic_to_shared(p);
}
__device__ __forceinline__ uint32_t swz(uint32_t off) {   // SW128-style XOR swizzle
    return off ^ ((off >> 3) & 0x70);
}
__device__ __forceinline__ void cp16(uint32_t dst, const void* src) {
    asm volatile("cp.async.cg.shared.global [%0], [%1], 16;\n" :: "r"(dst), "l"(src));
}
__device__ __forceinline__ void cp_commit() { asm volatile("cp.async.commit_group;\n"); }
template <int N>
__device__ __forceinline__ void cp_wait() { asm volatile("cp.async.wait_group %0;\n" :: "n"(N)); }

__device__ __forceinline__ void ldsm_x4(uint32_t* r, uint32_t addr) {
    asm volatile("ldmatrix.sync.aligned.m8n8.x4.shared.b16 {%0,%1,%2,%3}, [%4];\n"
                 : "=r"(r[0]), "=r"(r[1]), "=r"(r[2]), "=r"(r[3]) : "r"(addr));
}
__device__ __forceinline__ void mma16816(float* c, const uint32_t* a, const uint32_t* b) {
    asm volatile("mma.sync.aligned.m16n8k16.row.col.f32.f16.f16.f32 "
                 "{%0,%1,%2,%3}, {%4,%5,%6,%7}, {%8,%9}, {%0,%1,%2,%3};\n"
                 : "+f"(c[0]), "+f"(c[1]), "+f"(c[2]), "+f"(c[3])
                 : "r"(a[0]), "r"(a[1]), "r"(a[2]), "r"(a[3]), "r"(b[0]), "r"(b[1]));
}

// ---------------- fp16 GEMM:  C[M,N] = A[M,K] * W[N,K]^T + bias ----------------
// grid = (N/BN, M/BM). Grouped along M: group = bm / mRowsPerGroup.
template <typename OutT>
__global__ __launch_bounds__(256, 2)
void gemm_kernel(const __half* __restrict__ A, const __half* __restrict__ W,
                 const float* __restrict__ bias, OutT* __restrict__ C,
                 int N, int K, int mRowsPerGroup) {
    extern __shared__ char smem_raw[];
    const uint32_t sbase = smem_u32(smem_raw);

    const int tid  = threadIdx.x;
    const int lane = tid & 31;
    const int warp = tid >> 5;
    const int wm   = warp >> 2;   // 2 x 64 rows
    const int wn   = warp & 3;    // 4 x 32 cols
    const int bm   = blockIdx.y * BM;
    const int bn   = blockIdx.x * BN;
    const int group = bm / mRowsPerGroup;

    const __half* gA = A + (size_t)bm * K;
    const __half* gW = W + (size_t)group * N * K + (size_t)bn * K;
    const float*  gBias = bias + (size_t)group * N + bn;
    const int kTiles = K / BK;

    float acc[4][4][4];
#pragma unroll
    for (int a = 0; a < 4; a++)
#pragma unroll
        for (int b = 0; b < 4; b++)
#pragma unroll
            for (int c = 0; c < 4; c++) acc[a][b][c] = 0.f;

    auto load_stage = [&](int s, int kt) {
        const uint32_t dA = sbase + s * STG;
        const uint32_t dB = dA + ASTG;
        const __half* srcA = gA + kt * BK;
        const __half* srcB = gW + kt * BK;
#pragma unroll
        for (int i = 0; i < 4; i++) {       // A: 1024 chunks of 16B
            int q = tid + i * 256;
            int r = q >> 3, c = q & 7;
            cp16(dA + swz((uint32_t)(r * 128 + c * 16)), srcA + (size_t)r * K + c * 8);
        }
#pragma unroll
        for (int i = 0; i < 4; i++) {       // B: 1024 chunks of 16B
            int q = tid + i * 256;
            int r = q >> 3, c = q & 7;
            cp16(dB + swz((uint32_t)(r * 128 + c * 16)), srcB + (size_t)r * K + c * 8);
        }
    };

    // prologue: 2 stages in flight
    load_stage(0, 0); cp_commit();
    if (kTiles > 1) load_stage(1, 1);
    cp_commit();

    for (int kt = 0; kt < kTiles; ++kt) {
        cp_wait<1>();          // stage kt resident
        __syncthreads();       // all warps done with stage (kt-1) -> safe to overwrite

        // issue next-stage loads first so they overlap the MMAs below
        const int nk = kt + 2;
        if (nk < kTiles) load_stage(nk % STAGES, nk);
        cp_commit();

        const uint32_t cA = sbase + (kt % STAGES) * STG;
        const uint32_t cB = cA + ASTG;

#pragma unroll
        for (int ks = 0; ks < BK / 16; ++ks) {
            uint32_t aF[4][4], bF[4][2];
#pragma unroll
            for (int mi = 0; mi < 4; ++mi) {
                int r = wm * 64 + mi * 16 + (lane & 15);
                int c = ks * 16 + (lane >> 4) * 8;
                ldsm_x4(aF[mi], cA + swz((uint32_t)(r * 128 + c * 2)));
            }
#pragma unroll
            for (int np = 0; np < 2; ++np) {   // each ldsm.x4 covers 16 n-cols
                int r = wn * 32 + np * 16 + ((lane >> 4) & 1) * 8 + (lane & 7);
                int c = ks * 16 + ((lane >> 3) & 1) * 8;
                uint32_t t[4];
                ldsm_x4(t, cB + swz((uint32_t)(r * 128 + c * 2)));
                bF[2 * np][0] = t[0]; bF[2 * np][1] = t[1];
                bF[2 * np + 1][0] = t[2]; bF[2 * np + 1][1] = t[3];
            }
#pragma unroll
            for (int mi = 0; mi < 4; ++mi)
#pragma unroll
                for (int ni = 0; ni < 4; ++ni)
                    mma16816(acc[mi][ni], aF[mi], bF[ni]);
        }
    }

    // ---------------- epilogue: bias add + store ----------------
#pragma unroll
    for (int mi = 0; mi < 4; ++mi) {
#pragma unroll
        for (int ni = 0; ni < 4; ++ni) {
            int r0 = bm + wm * 64 + mi * 16 + (lane >> 2);
            int cb = wn * 32 + ni * 8 + (lane & 3) * 2;
            int c0 = bn + cb;
            float bv0 = gBias[cb], bv1 = gBias[cb + 1];
            float v0 = acc[mi][ni][0] + bv0;
            float v1 = acc[mi][ni][1] + bv1;
            float v2 = acc[mi][ni][2] + bv0;
            float v3 = acc[mi][ni][3] + bv1;
            if constexpr (sizeof(OutT) == 2) {
                *(__half2*)((__half*)C + (size_t)r0 * N + c0)       = __floats2half2_rn(v0, v1);
                *(__half2*)((__half*)C + (size_t)(r0 + 8) * N + c0) = __floats2half2_rn(v2, v3);
            } else {
                *(float2*)((float*)C + (size_t)r0 * N + c0)       = make_float2(v0, v1);
                *(float2*)((float*)C + (size_t)(r0 + 8) * N + c0) = make_float2(v2, v3);
            }
        }
    }
}

// ---------------- host launcher ----------------
static inline void* sym_addr(const void* symbol) {
    void* p = nullptr;
    cudaGetSymbolAddress(&p, symbol);
    return p;
}

extern "C" void kernel_launch(void* const* d_in, const int* in_sizes, int n_in,
                              void* d_out, int out_size) {
    const float* x    = (const float*)d_in[0];
    const float* w1   = (const float*)d_in[1];
    const float* b1   = (const float*)d_in[2];
    const float* w2   = (const float*)d_in[3];
    const float* b2   = (const float*)d_in[4];
    const float* g1w0 = (const float*)d_in[5];
    const float* g1b0 = (const float*)d_in[6];
    const float* g2w0 = (const float*)d_in[7];
    const float* g2b0 = (const float*)d_in[8];
    const float* g1w1 = (const float*)d_in[9];
    const float* g1b1 = (const float*)d_in[10];
    const float* g2w1 = (const float*)d_in[11];
    const float* g2b1 = (const float*)d_in[12];

    __half* bufA = (__half*)sym_addr(g_bufA);
    __half* bufB = (__half*)sym_addr(g_bufB);
    __half* w1h  = (__half*)sym_addr(g_w1h);
    __half* w2h  = (__half*)sym_addr(g_w2h);
    __half* l0g1 = (__half*)sym_addr(g_l0g1);
    __half* l0g2 = (__half*)sym_addr(g_l0g2);
    __half* l1g1 = (__half*)sym_addr(g_l1g1);
    __half* l1g2 = (__half*)sym_addr(g_l1g2);

    cudaFuncSetAttribute(gemm_kernel<__half>, cudaFuncAttributeMaxDynamicSharedMemorySize, SMEM_BYTES);
    cudaFuncSetAttribute(gemm_kernel<float>,  cudaFuncAttributeMaxDynamicSharedMemorySize, SMEM_BYTES);

    auto conv = [&](const float* s, __half* d, size_t n) {
        size_t n4 = n / 4;
        unsigned blocks = (unsigned)((n4 + 255) / 256);
        f2h_kernel<<<blocks, 256>>>((const float4*)s, (__half2*)d, n4);
    };

    conv(x,    bufA, (size_t)TOK * HD);
    conv(w1,   w1h,  (size_t)ID * HD);
    conv(w2,   w2h,  (size_t)HD * ID);
    conv(g1w0, l0g1, (size_t)NG * ID * HD);
    conv(g2w0, l0g2, (size_t)NG * HD * ID);
    conv(g1w1, l1g1, (size_t)NG * ID * HD);
    conv(g2w1, l1g2, (size_t)NG * HD * ID);

    dim3 blk(256);
    // stage 1: dense w1  [16384,2048] x [4096,2048]^T -> [16384,4096]
    gemm_kernel<__half><<<dim3(ID / BN, TOK / BM), blk, SMEM_BYTES>>>(bufA, w1h, b1, bufB, ID, HD, TOK);
    // stage 2: dense w2 -> [16384,2048]
    gemm_kernel<__half><<<dim3(HD / BN, TOK / BM), blk, SMEM_BYTES>>>(bufB, w2h, b2, bufA, HD, ID, TOK);
    // layer 0 grouped
    gemm_kernel<__half><<<dim3(ID / BN, TOK / BM), blk, SMEM_BYTES>>>(bufA, l0g1, g1b0, bufB, ID, HD, TOK / NG);
    gemm_kernel<__half><<<dim3(HD / BN, TOK / BM), blk, SMEM_BYTES>>>(bufB, l0g2, g2b0, bufA, HD, ID, TOK / NG);
    // layer 1 grouped
    gemm_kernel<__half><<<dim3(ID / BN, TOK / BM), blk, SMEM_BYTES>>>(bufA, l1g1, g1b1, bufB, ID, HD, TOK / NG);
    // final: fp32 straight to d_out
    gemm_kernel<float><<<dim3(HD / BN, TOK / BM), blk, SMEM_BYTES>>>(bufB, l1g2, g2b1, (float*)d_out, HD, ID, TOK / NG);
}